// round 3
// baseline (speedup 1.0000x reference)
#include <cuda_runtime.h>
#include <stdint.h>

#define BATCH 1024
#define KSEL  64
#define IFEAT 4096
#define OFEAT 4096

// Device scratch (static device global; no runtime alloc).
__device__ float g_WT[(size_t)IFEAT * OFEAT];   // 64 MB, W transposed: WT[c][o]

// ---------------------------------------------------------------------------
// Transpose W (O,I) -> WT (I,O). 64x64 tiles, float4 on both global sides.
// ---------------------------------------------------------------------------
__global__ __launch_bounds__(256) void transpose_kernel(const float* __restrict__ W)
{
    __shared__ float t[64][65];
    const int bc = blockIdx.x * 64;   // input-feature (column of W)
    const int br = blockIdx.y * 64;   // output-feature (row of W)
    const int tid = threadIdx.x;
    const int sub = tid & 15;         // 16 float4 per 64-wide row
    const int grp = tid >> 4;         // 16 rows per pass

#pragma unroll
    for (int p = 0; p < 4; ++p) {
        int row = p * 16 + grp;
        int c4  = sub * 4;
        float4 v = *reinterpret_cast<const float4*>(
            W + (size_t)(br + row) * IFEAT + bc + c4);
        t[c4 + 0][row] = v.x;
        t[c4 + 1][row] = v.y;
        t[c4 + 2][row] = v.z;
        t[c4 + 3][row] = v.w;
    }
    __syncthreads();
#pragma unroll
    for (int p = 0; p < 4; ++p) {
        int c  = p * 16 + grp;
        int o4 = sub * 4;
        float4 v = make_float4(t[c][o4], t[c][o4 + 1], t[c][o4 + 2], t[c][o4 + 3]);
        *reinterpret_cast<float4*>(g_WT + (size_t)(bc + c) * OFEAT + br + o4) = v;
    }
}

// ---------------------------------------------------------------------------
// Monotone key helpers (order-preserving float<->uint bijection).
// ---------------------------------------------------------------------------
__device__ __forceinline__ unsigned f2u(float f) {
    unsigned u = __float_as_uint(f);
    return (u & 0x80000000u) ? ~u : (u | 0x80000000u);
}
__device__ __forceinline__ float u2f(unsigned u) {
    unsigned b = (u & 0x80000000u) ? (u ^ 0x80000000u) : ~u;
    return __uint_as_float(b);
}

// ---------------------------------------------------------------------------
// Fused: per-sample gemv (exact sequential-k FMA chain per output, bias last)
// + exact top-64 (radix select + stable bitonic), all in one block.
// Block = 256 threads; thread t owns outputs {j*1024 + t*4 + e}, j<4, e<4.
// Every WT load is a fully-coalesced LDG.128 covering a contiguous 2KB slab.
// ---------------------------------------------------------------------------
__global__ __launch_bounds__(256) void fused_kernel(const float* __restrict__ x,
                                                    const int*   __restrict__ idx,
                                                    const float* __restrict__ bias,
                                                    float* __restrict__ out,
                                                    int out_size)
{
    __shared__ float sx[KSEL];
    __shared__ int   soff[KSEL];
    __shared__ unsigned su[OFEAT];
    __shared__ unsigned hist[256];
    __shared__ unsigned long long cand[256];
    __shared__ unsigned sh_prefix;
    __shared__ int sh_need;
    __shared__ int ncand;

    const int b   = blockIdx.x;
    const int tid = threadIdx.x;

    if (tid < KSEL) {
        sx[tid]   = x[b * KSEL + tid];
        soff[tid] = idx[b * KSEL + tid] * OFEAT;
    }
    __syncthreads();

    float4 a0 = make_float4(0.f, 0.f, 0.f, 0.f);
    float4 a1 = a0, a2 = a0, a3 = a0;

#pragma unroll 4
    for (int k = 0; k < KSEL; ++k) {
        const float xv = sx[k];
        const float4* p = reinterpret_cast<const float4*>(g_WT + soff[k]) + tid;
        float4 w0 = p[0], w1 = p[256], w2 = p[512], w3 = p[768];
        a0.x = fmaf(xv, w0.x, a0.x); a0.y = fmaf(xv, w0.y, a0.y);
        a0.z = fmaf(xv, w0.z, a0.z); a0.w = fmaf(xv, w0.w, a0.w);
        a1.x = fmaf(xv, w1.x, a1.x); a1.y = fmaf(xv, w1.y, a1.y);
        a1.z = fmaf(xv, w1.z, a1.z); a1.w = fmaf(xv, w1.w, a1.w);
        a2.x = fmaf(xv, w2.x, a2.x); a2.y = fmaf(xv, w2.y, a2.y);
        a2.z = fmaf(xv, w2.z, a2.z); a2.w = fmaf(xv, w2.w, a2.w);
        a3.x = fmaf(xv, w3.x, a3.x); a3.y = fmaf(xv, w3.y, a3.y);
        a3.z = fmaf(xv, w3.z, a3.z); a3.w = fmaf(xv, w3.w, a3.w);
    }

    // bias (added once, after the chain — matches reference) -> monotone keys
    {
        const float4* bp = reinterpret_cast<const float4*>(bias) + tid;
        float4 b0 = bp[0], b1 = bp[256], b2 = bp[512], b3 = bp[768];
        int o = tid * 4;
        su[o + 0]        = f2u(a0.x + b0.x);
        su[o + 1]        = f2u(a0.y + b0.y);
        su[o + 2]        = f2u(a0.z + b0.z);
        su[o + 3]        = f2u(a0.w + b0.w);
        su[o + 1024]     = f2u(a1.x + b1.x);
        su[o + 1025]     = f2u(a1.y + b1.y);
        su[o + 1026]     = f2u(a1.z + b1.z);
        su[o + 1027]     = f2u(a1.w + b1.w);
        su[o + 2048]     = f2u(a2.x + b2.x);
        su[o + 2049]     = f2u(a2.y + b2.y);
        su[o + 2050]     = f2u(a2.z + b2.z);
        su[o + 2051]     = f2u(a2.w + b2.w);
        su[o + 3072]     = f2u(a3.x + b3.x);
        su[o + 3073]     = f2u(a3.y + b3.y);
        su[o + 3074]     = f2u(a3.z + b3.z);
        su[o + 3075]     = f2u(a3.w + b3.w);
    }
    __syncthreads();

    // Radix-select exact rank-64 key T (descending).
    unsigned prefix = 0, mask = 0;
    int shift = 24, need = KSEL;
    for (int pass = 0; pass < 4; ++pass) {
        hist[tid] = 0;
        __syncthreads();
        for (int o = tid; o < OFEAT; o += 256) {
            unsigned u = su[o];
            if ((u & mask) == prefix)
                atomicAdd(&hist[(u >> shift) & 255], 1u);
        }
        __syncthreads();
        if (tid == 0) {
            int cum = 0;
            for (int bin = 255; bin >= 0; --bin) {
                cum += (int)hist[bin];
                if (cum >= need) {
                    sh_prefix = prefix | ((unsigned)bin << shift);
                    sh_need   = need - (cum - (int)hist[bin]);
                    break;
                }
            }
        }
        __syncthreads();
        prefix = sh_prefix;
        need   = sh_need;
        mask  |= (0xFFu << shift);
        shift -= 8;
    }
    const unsigned T = prefix;

    // Collect all u >= T.
    if (tid == 0) ncand = 0;
    cand[tid] = 0ull;
    __syncthreads();
    for (int o = tid; o < OFEAT; o += 256) {
        unsigned u = su[o];
        if (u >= T) {
            int p = atomicAdd(&ncand, 1);
            if (p < 256)
                cand[p] = ((unsigned long long)u << 32) | (unsigned)(4095 - o);
        }
    }
    __syncthreads();

    // Bitonic sort 256 keys descending (value desc, index asc on ties).
    for (int k2 = 2; k2 <= 256; k2 <<= 1) {
        for (int j2 = k2 >> 1; j2 > 0; j2 >>= 1) {
            int i = tid, ixj = tid ^ j2;
            if (ixj > i) {
                bool desc = ((i & k2) == 0);
                unsigned long long a = cand[i], bb = cand[ixj];
                if (desc ? (a < bb) : (a > bb)) { cand[i] = bb; cand[ixj] = a; }
            }
            __syncthreads();
        }
    }

    if (tid < KSEL) {
        unsigned long long key = cand[tid];
        unsigned u = (unsigned)(key >> 32);
        int o = 4095 - (int)(key & 0xFFFFFFFFull);
        int half = out_size >> 1;
        out[(size_t)b * KSEL + tid]        = u2f(u);
        out[(size_t)half + b * KSEL + tid] = (float)o;
    }
}

// ---------------------------------------------------------------------------
extern "C" void kernel_launch(void* const* d_in, const int* in_sizes, int n_in,
                              void* d_out, int out_size)
{
    const float* input  = nullptr;
    const float* weight = nullptr;
    const float* bias   = nullptr;
    const int*   idx    = nullptr;
    for (int i = 0; i < n_in; ++i) {
        if (in_sizes[i] == OFEAT * IFEAT)      weight = (const float*)d_in[i];
        else if (in_sizes[i] == OFEAT)         bias   = (const float*)d_in[i];
        else if (in_sizes[i] == BATCH * KSEL) {
            if (!input) input = (const float*)d_in[i];
            else        idx   = (const int*)d_in[i];
        }
    }

    transpose_kernel<<<dim3(IFEAT / 64, OFEAT / 64), 256>>>(weight);
    fused_kernel<<<BATCH, 256>>>(input, idx, bias, (float*)d_out, out_size);
}